// round 5
// baseline (speedup 1.0000x reference)
#include <cuda_runtime.h>
#include <cuda_fp16.h>
#include <math.h>

// ---------------------------------------------------------------------------
// SiamFC head, round 5.
//   H[b,r,j,p] = sum_{c,q} x'[b,c,r-8,j+q-8] * z'[b,c,p,q]   (HMMA fp16)
//   out[b,i,j] = 0.001 * sum_p H[b,i+p,j,p]
// corr: 2 rows/CTA, A-fragments via single LDG.128 from fragment-ordered ZA.
// prep_x: division-free, register-sliding 8-px strips.
// ---------------------------------------------------------------------------

__device__ __align__(16) unsigned XG[64 * 64 * 112 * 56];     // x' fp16 half2 words
__device__ __align__(16) unsigned ZA[(64 * 64 + 2) * 128];    // z' in A-frag order (+pad)
__device__ __align__(16) float Hbuf[64 * 112 * 16 * 112];     // H[b][r][p][j]

__device__ __forceinline__ float gelu_exact(float v) {
    return 0.5f * v * (1.0f + erff(v * 0.70710678118654752f));
}

// ---- Kernel A: preprocess x -> XG ---------------------------------------------
__global__ __launch_bounds__(192) void prep_x(const float* __restrict__ x,
                                              const float* __restrict__ wx,
                                              const float* __restrict__ bx) {
    int bc = blockIdx.x;        // b*64 + c
    int c  = bc & 63;
    int tid = threadIdx.x;
    __shared__ __align__(16) float sp[98 * 100];

    // zero halo (vectorized full clear)
    float4 z4 = make_float4(0.f, 0.f, 0.f, 0.f);
    for (int i = tid; i < 2450; i += 192) reinterpret_cast<float4*>(sp)[i] = z4;
    __syncthreads();

    // load 96x96 plane: tid -> (row parity, col); no divisions
    {
        int col = (tid < 96) ? tid : tid - 96;
        int rp  = (tid < 96) ? 0 : 1;
        const float* xp = x + (size_t)bc * 9216;
        for (int k = 0; k < 48; ++k) {
            int r = 2 * k + rp;
            sp[(r + 1) * 100 + (col + 1)] = xp[r * 96 + col];
        }
    }
    __syncthreads();

    float w[9];
#pragma unroll
    for (int k = 0; k < 9; ++k) w[k] = __ldg(wx + c * 9 + k);
    float bias = __ldg(bx + c);

    int v4 = tid % 12;          // col group (8 px), one div per thread
    int r0 = tid / 12;          // 0..15
    int xc0 = v4 * 8;

    uint4* dst = reinterpret_cast<uint4*>(XG + (size_t)bc * (112 * 56));
#pragma unroll 1
    for (int it = 0; it < 6; ++it) {
        int r = r0 + 16 * it;   // x row 0..95
        float rowv[3][12];
#pragma unroll
        for (int di = 0; di < 3; ++di) {
            const float4* src = reinterpret_cast<const float4*>(sp + (r + di) * 100 + xc0);
            float4 A = src[0], B = src[1], C = src[2];
            rowv[di][0] = A.x; rowv[di][1] = A.y; rowv[di][2]  = A.z; rowv[di][3]  = A.w;
            rowv[di][4] = B.x; rowv[di][5] = B.y; rowv[di][6]  = B.z; rowv[di][7]  = B.w;
            rowv[di][8] = C.x; rowv[di][9] = C.y; rowv[di][10] = C.z; rowv[di][11] = C.w;
        }
        unsigned ow[4];
#pragma unroll
        for (int t = 0; t < 4; ++t) {
            float f[2];
#pragma unroll
            for (int u = 0; u < 2; ++u) {
                int e = 2 * t + u;  // px within strip
                float conv = bias;
#pragma unroll
                for (int di = 0; di < 3; ++di)
#pragma unroll
                    for (int dj = 0; dj < 3; ++dj)
                        conv = fmaf(w[di * 3 + dj], rowv[di][e + dj], conv);
                f[u] = gelu_exact(rowv[1][e + 1] + conv);
            }
            __half2 h = __floats2half2_rn(f[0], f[1]);
            ow[t] = *reinterpret_cast<unsigned*>(&h);
        }
        dst[(r + 8) * 14 + 1 + v4] = make_uint4(ow[0], ow[1], ow[2], ow[3]);
    }
}

// ---- Kernel B: preprocess z -> ZA (A-fragment order) ---------------------------
__global__ __launch_bounds__(256) void prep_z(const float* __restrict__ z,
                                              const float* __restrict__ wz,
                                              const float* __restrict__ bz) {
    int bc = blockIdx.x;
    int c  = bc & 63;
    __shared__ float sp[18 * 18];

    for (int i = threadIdx.x; i < 18 * 18; i += 256) sp[i] = 0.0f;
    __syncthreads();

    int t = threadIdx.x;
    int p = t >> 4, q = t & 15;
    sp[(p + 1) * 18 + (q + 1)] = z[(size_t)bc * 256 + t];
    __syncthreads();

    float conv = __ldg(bz + c);
#pragma unroll
    for (int di = 0; di < 3; ++di)
#pragma unroll
        for (int dj = 0; dj < 3; ++dj)
            conv = fmaf(__ldg(wz + c * 9 + di * 3 + dj), sp[(p + di) * 18 + (q + dj)], conv);
    float val = gelu_exact(sp[(p + 1) * 18 + (q + 1)] + conv);

    // A-fragment placement for mma.m16n8k16 row-major A
    int lane = ((p & 7) << 2) | ((q & 7) >> 1);
    int reg  = ((p >> 3) & 1) | (((q >> 3) & 1) << 1);
    int h    = q & 1;
    reinterpret_cast<__half*>(ZA)[((size_t)bc * 32 + lane) * 8 + reg * 2 + h] =
        __float2half(val);
}

// ---- Kernel C: correlation GEMM, 2 rows/CTA ------------------------------------
// Grid (48, 64): rows r=8+2bx, r+1. 4 warps; warp w owns j-tiles {w,w+4,w+8,w+12}<13.
// Dynamic smem: 2 rows x (even 4096 + 16 pad + odd 4096) = 16416 words.
#define ROWW 8208
#define ODDO 4112
__global__ __launch_bounds__(128) void corr() {
    extern __shared__ unsigned sq[];
    int r = 8 + 2 * blockIdx.x, b = blockIdx.y;
    int tid = threadIdx.x, lane = tid & 31, w = tid >> 5;

    // Stage even copies (uint4), zero-fill words 56..63
    for (int t = tid; t < 2048; t += 128) {
        int rr = t >> 10, g = t & 1023, c = g >> 4, v = g & 15;
        uint4 d = make_uint4(0u, 0u, 0u, 0u);
        if (v < 14)
            d = __ldg(reinterpret_cast<const uint4*>(
                    XG + (size_t)(b * 64 + c) * 6272 + (size_t)(r + rr) * 56) + v);
        reinterpret_cast<uint4*>(sq)[rr * 2052 + (c << 4) + v] = d;
    }
    __syncthreads();
    // Build odd-shifted copies (uint4 + funnel shifts)
    for (int t = tid; t < 2048; t += 128) {
        int rr = t >> 10, g = t & 1023;
        int ebase = rr * ROWW + (g << 2);
        uint4 e = *reinterpret_cast<const uint4*>(sq + ebase);
        unsigned e4 = sq[ebase + 4];
        uint4 o;
        o.x = __funnelshift_r(e.x, e.y, 16);
        o.y = __funnelshift_r(e.y, e.z, 16);
        o.z = __funnelshift_r(e.z, e.w, 16);
        o.w = __funnelshift_r(e.w, e4, 16);
        reinterpret_cast<uint4*>(sq)[rr * 2052 + 1028 + g] = o;
    }
    __syncthreads();

    // Per-lane B-fragment base (within c-block)
    int nj = lane >> 2;
    int q0 = (lane & 3) << 1;
    int widx = (nj + q0) >> 1;
    const unsigned* e0 = sq + ((nj & 1) ? ODDO : 0) + widx + (w << 2);
    const unsigned* e1 = e0 + ROWW;

    const uint4* zp = reinterpret_cast<const uint4*>(ZA) + (size_t)b * 64 * 32 + lane;

    float acc[2][4][4];
#pragma unroll
    for (int rr = 0; rr < 2; ++rr)
#pragma unroll
        for (int u = 0; u < 4; ++u)
#pragma unroll
            for (int k = 0; k < 4; ++k) acc[rr][u][k] = 0.0f;

    uint4 a = __ldg(zp);
#pragma unroll 1
    for (int c = 0; c < 64; ++c) {
        uint4 an = __ldg(zp + (c + 1) * 32);   // ZA padded: safe at c=63
#pragma unroll
        for (int u = 0; u < 4; ++u) {
            if (w + 4 * u < 13) {
                unsigned b00 = e0[u * 16], b01 = e0[u * 16 + 4];
                asm volatile(
                    "mma.sync.aligned.m16n8k16.row.col.f32.f16.f16.f32 "
                    "{%0,%1,%2,%3}, {%4,%5,%6,%7}, {%8,%9}, {%0,%1,%2,%3};"
                    : "+f"(acc[0][u][0]), "+f"(acc[0][u][1]),
                      "+f"(acc[0][u][2]), "+f"(acc[0][u][3])
                    : "r"(a.x), "r"(a.y), "r"(a.z), "r"(a.w), "r"(b00), "r"(b01));
                unsigned b10 = e1[u * 16], b11 = e1[u * 16 + 4];
                asm volatile(
                    "mma.sync.aligned.m16n8k16.row.col.f32.f16.f16.f32 "
                    "{%0,%1,%2,%3}, {%4,%5,%6,%7}, {%8,%9}, {%0,%1,%2,%3};"
                    : "+f"(acc[1][u][0]), "+f"(acc[1][u][1]),
                      "+f"(acc[1][u][2]), "+f"(acc[1][u][3])
                    : "r"(a.x), "r"(a.y), "r"(a.z), "r"(a.w), "r"(b10), "r"(b11));
            }
        }
        a = an;
        e0 += 64; e1 += 64;
    }

    // Store H for both rows
    int p0 = lane >> 2, jn = (lane & 3) << 1;
#pragma unroll
    for (int rr = 0; rr < 2; ++rr) {
        float* Hb = Hbuf + (size_t)(b * 112 + r + rr) * (16 * 112);
#pragma unroll
        for (int u = 0; u < 4; ++u) {
            int jt = w + 4 * u;
            if (jt < 13) {
                int j = jt * 8 + jn;
                *reinterpret_cast<float2*>(Hb + p0 * 112 + j) =
                    make_float2(acc[rr][u][0], acc[rr][u][1]);
                *reinterpret_cast<float2*>(Hb + (p0 + 8) * 112 + j) =
                    make_float2(acc[rr][u][2], acc[rr][u][3]);
            }
        }
    }
}

// ---- Kernel D: shift-add epilogue -----------------------------------------------
__global__ __launch_bounds__(256) void epilogue(float* __restrict__ out) {
    int t = blockIdx.x * 256 + threadIdx.x;
    if (t >= 64 * 97 * 97) return;
    int b = t / 9409, rem = t - b * 9409;
    int i = rem / 97, j = rem - i * 97;
    const float* Hb = Hbuf + (size_t)b * (112 * 16 * 112);
    float s = 0.0f;
#pragma unroll
    for (int p = 0; p < 16; ++p)
        s += Hb[(size_t)((i + p) * 16 + p) * 112 + j];
    out[t] = s * 0.001f;
}

// ---- launch -----------------------------------------------------------------------
extern "C" void kernel_launch(void* const* d_in, const int* in_sizes, int n_in,
                              void* d_out, int out_size) {
    const float* z  = (const float*)d_in[0];
    const float* x  = (const float*)d_in[1];
    const float* wz = (const float*)d_in[2];
    const float* bz = (const float*)d_in[3];
    const float* wx = (const float*)d_in[4];
    const float* bx = (const float*)d_in[5];
    float* out = (float*)d_out;

    static int smem_set = 0;
    const int SMEM = 2 * ROWW * 4;  // 65664 bytes
    if (!smem_set) {
        cudaFuncSetAttribute(corr, cudaFuncAttributeMaxDynamicSharedMemorySize, SMEM);
        smem_set = 1;
    }

    prep_x<<<4096, 192>>>(x, wx, bx);
    prep_z<<<4096, 256>>>(z, wz, bz);
    corr<<<dim3(48, 64), 128, SMEM>>>();
    epilogue<<<(64 * 97 * 97 + 255) / 256, 256>>>(out);
}